// round 1
// baseline (speedup 1.0000x reference)
#include <cuda_runtime.h>

#define B_   8
#define N_   4096
#define D_   1024
#define EMB_ 64
#define CLN_ 10

// Scratch (allocation-free rule: __device__ globals)
__device__ float g_sums[B_ * CLN_ * EMB_];
__device__ float g_cnts[B_ * CLN_];
__device__ float g_W1t[D_ * EMB_];   // W1 transposed: [k][e]

// ---------------------------------------------------------------------------
// Kernel 0: zero segment scratch + transpose W1 (64K elems)
// ---------------------------------------------------------------------------
__global__ void init_kernel(const float* __restrict__ W1) {
    int idx = blockIdx.x * 256 + threadIdx.x;        // 0 .. 65535
    if (idx < D_ * EMB_) {
        int k = idx >> 6;
        int e = idx & 63;
        g_W1t[idx] = W1[e * D_ + k];                 // W1 is [EMB][D]
    }
    if (idx < B_ * CLN_ * EMB_) g_sums[idx] = 0.0f;
    if (idx < B_ * CLN_)        g_cnts[idx] = 0.0f;
}

// ---------------------------------------------------------------------------
// Kernel 1: fused embed GEMM (+bias+ReLU) + per-cluster segment reduction.
// Block = 256 threads, 128 patches, full EMB=64 output.
// Thread tile: 4 patches x 8 embeddings, accumulated as 4x4 f32x2 pairs
// via fma.rn.f32x2 (FFMA2: 2x fp32 throughput on sm_103a).
// ---------------------------------------------------------------------------
__global__ void __launch_bounds__(256, 3)
embed_kernel(const float* __restrict__ data,
             const int*   __restrict__ labels,
             const float* __restrict__ b1) {
    __shared__ float As[128 * 33];        // data tile [patch][k], pad 33
    __shared__ float Bs[32 * 64];         // weight tile [k][e]
    __shared__ float csum[CLN_ * EMB_];   // per-cluster partial sums
    __shared__ float ccnt[CLN_];
    __shared__ float b1s[EMB_];

    const int tid = threadIdx.x;
    const int b   = blockIdx.y;
    const int p0  = blockIdx.x * 128;
    const int tx  = tid & 7;              // embedding group (8 groups of 8)
    const int ty  = tid >> 3;             // patch group (32 groups of 4)

    if (tid < EMB_) b1s[tid] = b1[tid];
    for (int i = tid; i < CLN_ * EMB_; i += 256) csum[i] = 0.0f;
    if (tid < CLN_) ccnt[tid] = 0.0f;

    unsigned long long acc[4][4];
#pragma unroll
    for (int i = 0; i < 4; i++)
#pragma unroll
        for (int j = 0; j < 4; j++) acc[i][j] = 0ull;

    const float* dptr = data + (size_t)(b * N_ + p0) * D_;

    for (int kt = 0; kt < D_; kt += 32) {
        __syncthreads();
        // Load data tile: 128 x 32, coalesced (warp reads one 128B row chunk)
#pragma unroll
        for (int l = 0; l < 16; l++) {
            int idx = tid + l * 256;
            int r = idx >> 5, k = idx & 31;
            As[r * 33 + k] = dptr[(size_t)r * D_ + kt + k];
        }
        // Load weight tile from pre-transposed W1t: coalesced
#pragma unroll
        for (int l = 0; l < 8; l++) {
            int idx = tid + l * 256;
            int k = idx >> 6, e = idx & 63;
            Bs[k * 64 + e] = g_W1t[(kt + k) * 64 + e];
        }
        __syncthreads();

#pragma unroll
        for (int kk = 0; kk < 32; kk++) {
            unsigned long long a2[4], b2[4];
#pragma unroll
            for (int i = 0; i < 4; i++) {
                float av = As[(ty * 4 + i) * 33 + kk];
                asm("mov.b64 %0, {%1, %1};" : "=l"(a2[i]) : "f"(av));
            }
#pragma unroll
            for (int j = 0; j < 4; j++)
                b2[j] = *reinterpret_cast<const unsigned long long*>(
                            &Bs[kk * 64 + tx * 8 + j * 2]);   // LDS.64, conflict-free
#pragma unroll
            for (int i = 0; i < 4; i++)
#pragma unroll
                for (int j = 0; j < 4; j++)
                    asm("fma.rn.f32x2 %0, %1, %2, %0;"
                        : "+l"(acc[i][j]) : "l"(a2[i]), "l"(b2[j]));
        }
    }
    __syncthreads();

    // bias + ReLU, then segment-accumulate into shared cluster sums
#pragma unroll
    for (int i = 0; i < 4; i++) {
        int p   = ty * 4 + i;
        int lab = labels[b * N_ + p0 + p];
        float* crow = &csum[lab * EMB_];
#pragma unroll
        for (int j = 0; j < 4; j++) {
            float lo, hi;
            asm("mov.b64 {%0, %1}, %2;" : "=f"(lo), "=f"(hi) : "l"(acc[i][j]));
            int e = tx * 8 + j * 2;
            lo = fmaxf(lo + b1s[e],     0.0f);
            hi = fmaxf(hi + b1s[e + 1], 0.0f);
            atomicAdd(&crow[e],     lo);
            atomicAdd(&crow[e + 1], hi);
        }
        if (tx == 0) atomicAdd(&ccnt[lab], 1.0f);
    }
    __syncthreads();

    // Flush block-level partials to global
    for (int i = tid; i < CLN_ * EMB_; i += 256)
        atomicAdd(&g_sums[b * CLN_ * EMB_ + i], csum[i]);
    if (tid < CLN_)
        atomicAdd(&g_cnts[b * CLN_ + tid], ccnt[tid]);
}

// ---------------------------------------------------------------------------
// Kernel 2: attention head + masked softmax + fc6. One block per batch.
// ---------------------------------------------------------------------------
__global__ void head_kernel(const float* __restrict__ Wa1, const float* __restrict__ ba1,
                            const float* __restrict__ Wa2, const float* __restrict__ ba2,
                            const float* __restrict__ Wf1, const float* __restrict__ bf1,
                            const float* __restrict__ Wf2, const float* __restrict__ bf2,
                            float* __restrict__ out) {
    __shared__ float h[CLN_][EMB_];
    __shared__ float u[CLN_][32];
    __shared__ float score[CLN_], Avec[CLN_], mask[CLN_];
    __shared__ float Mv[EMB_], f[32];

    const int b   = blockIdx.x;
    const int tid = threadIdx.x;   // 64 threads

    for (int c = 0; c < CLN_; c++) {
        float cnt = g_cnts[b * CLN_ + c];
        h[c][tid] = g_sums[(b * CLN_ + c) * EMB_ + tid] / fmaxf(cnt, 1.0f);
        if (tid == 0) mask[c] = (cnt > 0.0f) ? 1.0f : 0.0f;
    }
    __syncthreads();

    if (tid < 32) {
        for (int c = 0; c < CLN_; c++) {
            float s = ba1[tid];
            for (int e = 0; e < EMB_; e++) s += h[c][e] * Wa1[tid * EMB_ + e];
            u[c][tid] = tanhf(s);
        }
    }
    __syncthreads();

    if (tid < CLN_) {
        float s = ba2[0];
        for (int k = 0; k < 32; k++) s += u[tid][k] * Wa2[k];
        score[tid] = s;
    }
    __syncthreads();

    if (tid == 0) {
        // faithful masked softmax: max over x*mask + (1 - 1/(mask+1e-5))
        float xmax = -1e30f;
        for (int c = 0; c < CLN_; c++) {
            float xm = score[c] * mask[c] + (1.0f - 1.0f / (mask[c] + 1e-5f));
            xmax = fmaxf(xmax, xm);
        }
        float ssum = 0.0f;
        for (int c = 0; c < CLN_; c++) {
            float ex = expf(score[c] - xmax) * mask[c];
            Avec[c] = ex;
            ssum += ex;
        }
        for (int c = 0; c < CLN_; c++) Avec[c] /= ssum;
    }
    __syncthreads();

    {
        float m = 0.0f;
        for (int c = 0; c < CLN_; c++) m += Avec[c] * h[c][tid];
        Mv[tid] = m;
    }
    __syncthreads();

    if (tid < 32) {
        float s = bf1[tid];
        for (int e = 0; e < EMB_; e++) s += Mv[e] * Wf1[tid * EMB_ + e];
        f[tid] = fmaxf(s, 0.0f);
    }
    __syncthreads();

    if (tid == 0) {
        float s = bf2[0];
        for (int k = 0; k < 32; k++) s += f[k] * Wf2[k];
        out[b] = s;
    }
}

// ---------------------------------------------------------------------------
extern "C" void kernel_launch(void* const* d_in, const int* in_sizes, int n_in,
                              void* d_out, int out_size) {
    const float* data   = (const float*)d_in[0];
    const int*   labels = (const int*)  d_in[1];
    const float* W1     = (const float*)d_in[2];
    const float* b1     = (const float*)d_in[3];
    const float* Wa1    = (const float*)d_in[4];
    const float* ba1    = (const float*)d_in[5];
    const float* Wa2    = (const float*)d_in[6];
    const float* ba2    = (const float*)d_in[7];
    const float* Wf1    = (const float*)d_in[8];
    const float* bf1    = (const float*)d_in[9];
    const float* Wf2    = (const float*)d_in[10];
    const float* bf2    = (const float*)d_in[11];

    init_kernel<<<256, 256>>>(W1);
    embed_kernel<<<dim3(N_ / 128, B_), 256>>>(data, labels, b1);
    head_kernel<<<B_, 64>>>(Wa1, ba1, Wa2, ba2, Wf1, bf1, Wf2, bf2, (float*)d_out);
}

// round 3
// speedup vs baseline: 2.8925x; 2.8925x over previous
#include <cuda_runtime.h>
#include <cuda_fp16.h>
#include <cstdint>

#define B_     8
#define N_     4096
#define D_     1024
#define EMB_   64
#define CLN_   10
#define TILE_M 64
#define KC_    64                  // k-chunk (fp16 -> 128B rows)
#define NCHUNK (D_ / KC_)          // 16
#define NWARP  4
#define NTHR   128

// ---------------- device scratch (allocation-free rule) ----------------
__device__ float g_sums[B_ * CLN_ * EMB_];
__device__ float g_cnts[B_ * CLN_];
__device__ __align__(16) __half g_W1hi[EMB_ * D_];   // [e][k] row-major
__device__ __align__(16) __half g_W1lo[EMB_ * D_];

// ---------------- dynamic smem layout (bytes) ----------------
#define SM_B1S   0                 // 64 f
#define SM_LABS  256               // 64 int
#define SM_CSUM  512               // 640 f -> ends 3072
#define SM_BUF   4096              // 1024-aligned
#define AHI_OFF  0                 // 64 x 128B = 8KB
#define ALO_OFF  8192
#define BHI_OFF  16384
#define BLO_OFF  24576
#define BUF_BYTES 32768
#define SMEM_TOTAL (SM_BUF + 2 * BUF_BYTES)   // 69632

__device__ __forceinline__ uint32_t smem_u32(const void* p) {
    uint32_t a;
    asm("{ .reg .u64 t; cvta.to.shared.u64 t, %1; cvt.u32.u64 %0, t; }" : "=r"(a) : "l"(p));
    return a;
}
__device__ __forceinline__ uint32_t sw128(uint32_t o) { return o ^ ((o >> 3) & 0x70); }

__device__ __forceinline__ void ldmx4(uint32_t* r, uint32_t addr) {
    asm volatile("ldmatrix.sync.aligned.m8n8.x4.shared.b16 {%0,%1,%2,%3}, [%4];"
                 : "=r"(r[0]), "=r"(r[1]), "=r"(r[2]), "=r"(r[3]) : "r"(addr));
}
__device__ __forceinline__ void mma16816(float* c, const uint32_t* a, uint32_t b0, uint32_t b1) {
    asm volatile("mma.sync.aligned.m16n8k16.row.col.f32.f16.f16.f32 "
                 "{%0,%1,%2,%3}, {%4,%5,%6,%7}, {%8,%9}, {%0,%1,%2,%3};"
                 : "+f"(c[0]), "+f"(c[1]), "+f"(c[2]), "+f"(c[3])
                 : "r"(a[0]), "r"(a[1]), "r"(a[2]), "r"(a[3]), "r"(b0), "r"(b1));
}
__device__ __forceinline__ void cpasync16(uint32_t saddr, const void* gaddr) {
    asm volatile("cp.async.cg.shared.global [%0], [%1], 16;" :: "r"(saddr), "l"(gaddr));
}

// ---------------------------------------------------------------------------
// Kernel 0: zero segment scratch + split-convert W1 to fp16 hi/lo
// ---------------------------------------------------------------------------
__global__ void init_kernel(const float* __restrict__ W1) {
    int idx = blockIdx.x * 256 + threadIdx.x;   // 0..65535
    if (idx < EMB_ * D_) {
        float w = W1[idx];
        __half hi = __float2half_rn(w);
        g_W1hi[idx] = hi;
        g_W1lo[idx] = __float2half_rn(w - __half2float(hi));
    }
    if (idx < B_ * CLN_ * EMB_) g_sums[idx] = 0.0f;
    if (idx < B_ * CLN_)        g_cnts[idx] = 0.0f;
}

// ---------------------------------------------------------------------------
// Kernel 1: fp16-split mma.sync GEMM (+bias+ReLU) + per-cluster reduction.
// CTA: 64 patches x EMB=64, K=1024 in 16 chunks, double-buffered smem,
// LDG->reg prefetch for A (fp32->fp16 hi/lo cvt), cp.async for B.
// ---------------------------------------------------------------------------
__global__ void __launch_bounds__(NTHR)
embed_kernel(const float* __restrict__ data,
             const int*   __restrict__ labels,
             const float* __restrict__ b1) {
    extern __shared__ char smem[];
    const uint32_t sb = smem_u32(smem);
    const int tid  = threadIdx.x;
    const int warp = tid >> 5;
    const int lane = tid & 31;
    const int b    = blockIdx.y;
    const int p0   = blockIdx.x * TILE_M;

    float* b1s  = (float*)(smem + SM_B1S);
    int*   labs = (int*)  (smem + SM_LABS);
    float* csum = (float*)(smem + SM_CSUM);

    if (tid < EMB_)   b1s[tid]  = b1[tid];
    if (tid < TILE_M) labs[tid] = labels[b * N_ + p0 + tid];
    for (int i = tid; i < CLN_ * EMB_; i += NTHR) csum[i] = 0.0f;

    const float* dbase = data + (size_t)(b * N_ + p0) * D_;

    const int ar = tid >> 4;          // A fill row (per float4 slot)
    const int aq = tid & 15;
    const int br = tid >> 3;          // B fill row (per 16B slot)
    const int bq = tid & 7;

    // ---- prologue: fill chunk 0 into buf 0 ----
    {
        const uint32_t bufa = sb + SM_BUF;
#pragma unroll
        for (int l = 0; l < 4; l++) {
            int r = br + l * 16;
            uint32_t sw = sw128((uint32_t)(r * 128 + bq * 16));
            cpasync16(bufa + BHI_OFF + sw, g_W1hi + r * D_ + bq * 8);
            cpasync16(bufa + BLO_OFF + sw, g_W1lo + r * D_ + bq * 8);
        }
        asm volatile("cp.async.commit_group;");
#pragma unroll
        for (int l = 0; l < 8; l++) {
            int r = ar + l * 8;
            float4 v = *(const float4*)(dbase + (size_t)r * D_ + aq * 4);
            __half2 h0 = __floats2half2_rn(v.x, v.y);
            __half2 h1 = __floats2half2_rn(v.z, v.w);
            float2 f0 = __half22float2(h0), f1 = __half22float2(h1);
            __half2 l0 = __floats2half2_rn(v.x - f0.x, v.y - f0.y);
            __half2 l1 = __floats2half2_rn(v.z - f1.x, v.w - f1.y);
            uint32_t sw = sw128((uint32_t)(r * 128 + aq * 8));
            uint2 hv, lv;
            hv.x = *(uint32_t*)&h0; hv.y = *(uint32_t*)&h1;
            lv.x = *(uint32_t*)&l0; lv.y = *(uint32_t*)&l1;
            *(uint2*)(smem + SM_BUF + AHI_OFF + sw) = hv;
            *(uint2*)(smem + SM_BUF + ALO_OFF + sw) = lv;
        }
        asm volatile("cp.async.wait_group 0;");
    }
    __syncthreads();

    float acc[8][4];
#pragma unroll
    for (int nt = 0; nt < 8; nt++)
#pragma unroll
        for (int i = 0; i < 4; i++) acc[nt][i] = 0.0f;

    const uint32_t arow  = (uint32_t)(warp * 16 + (lane & 15));
    const uint32_t acolb = (uint32_t)((lane >> 4) * 16);
    const uint32_t brow8 = (uint32_t)(((lane >> 4) & 1) * 8 + (lane & 7));
    const uint32_t bkb   = (uint32_t)(((lane >> 3) & 1) * 16);

    for (int c = 0; c < NCHUNK; c++) {
        const int bi = c & 1;
        const int ni = bi ^ 1;
        const uint32_t bufa  = sb + SM_BUF + bi * BUF_BYTES;
        const uint32_t nbufa = sb + SM_BUF + ni * BUF_BYTES;
        char* nbuf = smem + SM_BUF + ni * BUF_BYTES;

        // ---- issue next chunk's loads (B via cp.async, A via LDG->regs) ----
        float4 pre[8];
        if (c + 1 < NCHUNK) {
            const int kc = (c + 1) * KC_;
#pragma unroll
            for (int l = 0; l < 4; l++) {
                int r = br + l * 16;
                uint32_t sw = sw128((uint32_t)(r * 128 + bq * 16));
                cpasync16(nbufa + BHI_OFF + sw, g_W1hi + r * D_ + kc + bq * 8);
                cpasync16(nbufa + BLO_OFF + sw, g_W1lo + r * D_ + kc + bq * 8);
            }
            asm volatile("cp.async.commit_group;");
#pragma unroll
            for (int l = 0; l < 8; l++) {
                int r = ar + l * 8;
                pre[l] = *(const float4*)(dbase + (size_t)r * D_ + kc + aq * 4);
            }
        }

        // ---- MMA over current chunk: 4 k16 steps ----
#pragma unroll
        for (int ks = 0; ks < 4; ks++) {
            uint32_t ah[4], al[4];
            uint32_t aoff = sw128(arow * 128 + (uint32_t)(ks * 32) + acolb);
            ldmx4(ah, bufa + AHI_OFF + aoff);
            ldmx4(al, bufa + ALO_OFF + aoff);
#pragma unroll
            for (int j = 0; j < 4; j++) {
                uint32_t bh[4], bl[4];
                uint32_t boff = sw128((uint32_t)(j * 16) * 128 + brow8 * 128 +
                                      (uint32_t)(ks * 32) + bkb);
                ldmx4(bh, bufa + BHI_OFF + boff);
                ldmx4(bl, bufa + BLO_OFF + boff);
                mma16816(acc[2 * j],     ah, bh[0], bh[1]);
                mma16816(acc[2 * j],     ah, bl[0], bl[1]);
                mma16816(acc[2 * j],     al, bh[0], bh[1]);
                mma16816(acc[2 * j + 1], ah, bh[2], bh[3]);
                mma16816(acc[2 * j + 1], ah, bl[2], bl[3]);
                mma16816(acc[2 * j + 1], al, bh[2], bh[3]);
            }
        }

        // ---- convert + store next A chunk ----
        if (c + 1 < NCHUNK) {
#pragma unroll
            for (int l = 0; l < 8; l++) {
                int r = ar + l * 8;
                float4 v = pre[l];
                __half2 h0 = __floats2half2_rn(v.x, v.y);
                __half2 h1 = __floats2half2_rn(v.z, v.w);
                float2 f0 = __half22float2(h0), f1 = __half22float2(h1);
                __half2 l0 = __floats2half2_rn(v.x - f0.x, v.y - f0.y);
                __half2 l1 = __floats2half2_rn(v.z - f1.x, v.w - f1.y);
                uint32_t sw = sw128((uint32_t)(r * 128 + aq * 8));
                uint2 hv, lv;
                hv.x = *(uint32_t*)&h0; hv.y = *(uint32_t*)&h1;
                lv.x = *(uint32_t*)&l0; lv.y = *(uint32_t*)&l1;
                *(uint2*)(nbuf + AHI_OFF + sw) = hv;
                *(uint2*)(nbuf + ALO_OFF + sw) = lv;
            }
            asm volatile("cp.async.wait_group 0;");
        }
        __syncthreads();
    }

    // ---- epilogue: bias + ReLU -> smem e-tile (stride 66), column reduction ----
    float* etile = (float*)(smem + SM_BUF);     // 64 x 66 floats = 16896B (buf0 free)
    {
        int r0 = warp * 16 + (lane >> 2);
        int cq = 2 * (lane & 3);
#pragma unroll
        for (int nt = 0; nt < 8; nt++) {
            int col = nt * 8 + cq;
            float bv0 = b1s[col], bv1 = b1s[col + 1];
            etile[r0 * 66 + col]           = fmaxf(acc[nt][0] + bv0, 0.0f);
            etile[r0 * 66 + col + 1]       = fmaxf(acc[nt][1] + bv1, 0.0f);
            etile[(r0 + 8) * 66 + col]     = fmaxf(acc[nt][2] + bv0, 0.0f);
            etile[(r0 + 8) * 66 + col + 1] = fmaxf(acc[nt][3] + bv1, 0.0f);
        }
    }
    __syncthreads();

    if (tid < EMB_) {
        // column-owner serial segment reduction: no atomics
        for (int r = 0; r < TILE_M; r++)
            csum[labs[r] * EMB_ + tid] += etile[r * 66 + tid];
    }
    if (tid < CLN_) {
        int cnt = 0;
        for (int r = 0; r < TILE_M; r++) cnt += (labs[r] == tid);
        if (cnt) atomicAdd(&g_cnts[b * CLN_ + tid], (float)cnt);
    }
    __syncthreads();

    for (int i = tid; i < CLN_ * EMB_; i += NTHR)
        atomicAdd(&g_sums[b * CLN_ * EMB_ + i], csum[i]);
}

// ---------------------------------------------------------------------------
// Kernel 2: attention head + masked softmax + fc6. One block per batch.
// ---------------------------------------------------------------------------
__global__ void head_kernel(const float* __restrict__ Wa1, const float* __restrict__ ba1,
                            const float* __restrict__ Wa2, const float* __restrict__ ba2,
                            const float* __restrict__ Wf1, const float* __restrict__ bf1,
                            const float* __restrict__ Wf2, const float* __restrict__ bf2,
                            float* __restrict__ out) {
    __shared__ float h[CLN_][EMB_];
    __shared__ float u[CLN_][32];
    __shared__ float score[CLN_], Avec[CLN_], mask[CLN_];
    __shared__ float Mv[EMB_], f[32];

    const int b   = blockIdx.x;
    const int tid = threadIdx.x;   // 64 threads

    for (int c = 0; c < CLN_; c++) {
        float cnt = g_cnts[b * CLN_ + c];
        h[c][tid] = g_sums[(b * CLN_ + c) * EMB_ + tid] / fmaxf(cnt, 1.0f);
        if (tid == 0) mask[c] = (cnt > 0.0f) ? 1.0f : 0.0f;
    }
    __syncthreads();

    if (tid < 32) {
        for (int c = 0; c < CLN_; c++) {
            float s = ba1[tid];
            for (int e = 0; e < EMB_; e++) s += h[c][e] * Wa1[tid * EMB_ + e];
            u[c][tid] = tanhf(s);
        }
    }
    __syncthreads();

    if (tid < CLN_) {
        float s = ba2[0];
        for (int k = 0; k < 32; k++) s += u[tid][k] * Wa2[k];
        score[tid] = s;
    }
    __syncthreads();

    if (tid == 0) {
        float xmax = -1e30f;
        for (int c = 0; c < CLN_; c++) {
            float xm = score[c] * mask[c] + (1.0f - 1.0f / (mask[c] + 1e-5f));
            xmax = fmaxf(xmax, xm);
        }
        float ssum = 0.0f;
        for (int c = 0; c < CLN_; c++) {
            float ex = expf(score[c] - xmax) * mask[c];
            Avec[c] = ex;
            ssum += ex;
        }
        for (int c = 0; c < CLN_; c++) Avec[c] /= ssum;
    }
    __syncthreads();

    {
        float m = 0.0f;
        for (int c = 0; c < CLN_; c++) m += Avec[c] * h[c][tid];
        Mv[tid] = m;
    }
    __syncthreads();

    if (tid < 32) {
        float s = bf1[tid];
        for (int e = 0; e < EMB_; e++) s += Mv[e] * Wf1[tid * EMB_ + e];
        f[tid] = fmaxf(s, 0.0f);
    }
    __syncthreads();

    if (tid == 0) {
        float s = bf2[0];
        for (int k = 0; k < 32; k++) s += f[k] * Wf2[k];
        out[b] = s;
    }
}

// ---------------------------------------------------------------------------
extern "C" void kernel_launch(void* const* d_in, const int* in_sizes, int n_in,
                              void* d_out, int out_size) {
    const float* data   = (const float*)d_in[0];
    const int*   labels = (const int*)  d_in[1];
    const float* W1     = (const float*)d_in[2];
    const float* b1     = (const float*)d_in[3];
    const float* Wa1    = (const float*)d_in[4];
    const float* ba1    = (const float*)d_in[5];
    const float* Wa2    = (const float*)d_in[6];
    const float* ba2    = (const float*)d_in[7];
    const float* Wf1    = (const float*)d_in[8];
    const float* bf1    = (const float*)d_in[9];
    const float* Wf2    = (const float*)d_in[10];
    const float* bf2    = (const float*)d_in[11];

    cudaFuncSetAttribute(embed_kernel, cudaFuncAttributeMaxDynamicSharedMemorySize,
                         SMEM_TOTAL);

    init_kernel<<<256, 256>>>(W1);
    embed_kernel<<<dim3(N_ / TILE_M, B_), NTHR, SMEM_TOTAL>>>(data, labels, b1);
    head_kernel<<<B_, 64>>>(Wa1, ba1, Wa2, ba2, Wf1, bf1, Wf2, bf2, (float*)d_out);
}